// round 3
// baseline (speedup 1.0000x reference)
#include <cuda_runtime.h>
#include <math.h>

#define B_ 256
#define T_ 1024
#define V_ 96
#define H_ 128

typedef unsigned long long ull;

// Device-global scratch (allocation-free per harness rules)
__device__ __align__(16) float g_proj[V_ * H_];       // emb @ W_ih0^T + b_ih0 + b_hh0
__device__ __align__(16) float g_y0[B_ * T_ * H_];    // layer-0 outputs      (128MB)
__device__ __align__(16) float g_xp1[B_ * T_ * H_];   // y0 @ W_ih1^T + b1    (128MB)
__device__ __align__(16) float g_y1[B_ * T_ * H_];    // layer-1 outputs      (128MB)

// packed fp32x2 FMA (Blackwell FFMA2)
__device__ __forceinline__ ull ffma2(ull a, ull b, ull c) {
    ull d;
    asm("fma.rn.f32x2 %0, %1, %2, %3;" : "=l"(d) : "l"(a), "l"(b), "l"(c));
    return d;
}
__device__ __forceinline__ float hadd(ull a) {
    float x, y;
    asm("mov.b64 {%0, %1}, %2;" : "=f"(x), "=f"(y) : "l"(a));
    return x + y;
}

// ---------------------------------------------------------------------------
// Projected embedding table: g_proj[v][j] = sum_h emb[v][h]*W_ih0[j][h] + b
// ---------------------------------------------------------------------------
__global__ void k_proj(const float* __restrict__ emb, const float* __restrict__ Wih0,
                       const float* __restrict__ bih0, const float* __restrict__ bhh0) {
    __shared__ float er[H_];
    int v = blockIdx.x, j = threadIdx.x;
    er[j] = emb[v * H_ + j];
    __syncthreads();
    float s = bih0[j] + bhh0[j];
    const float* wr = Wih0 + j * H_;
#pragma unroll 8
    for (int h = 0; h < H_; h++) s += er[h] * wr[h];
    g_proj[v * H_ + j] = s;
}

// ---------------------------------------------------------------------------
// Layer-0 recurrence. 256 CTAs (1 batch each) x 256 threads, 2 CTAs/SM.
// Thread (j = tid>>1, kh = tid&1). One shfl reduce, double-buffered h,
// one barrier per step. proj addend streamed via 2-deep register prefetch.
// ---------------------------------------------------------------------------
__global__ void __launch_bounds__(256, 2)
k_l0(const int* __restrict__ x, const float* __restrict__ Whh0, float* __restrict__ hid0) {
    __shared__ __align__(16) float h_s[2][128];
    __shared__ int x_s[T_];

    int tid = threadIdx.x;
    int j = tid >> 1, kh = tid & 1;
    int b = blockIdx.x;

    ull w[32];
    const ull* Wp = (const ull*)Whh0;
    int wbase = j * 64 + kh * 32;          // pairs for k in [kh*64, kh*64+64)
#pragma unroll
    for (int i = 0; i < 32; i++) w[i] = Wp[wbase + i];

    for (int i = tid; i < T_; i += 256) x_s[i] = x[b * T_ + i];
    if (tid < 128) h_s[0][tid] = 0.0f;
    __syncthreads();

    float p_cur = g_proj[x_s[0] * H_ + j];
    float p_nxt = g_proj[x_s[1] * H_ + j];

    float nh = 0.0f;
    for (int t = 0; t < T_; t++) {
        const ulonglong2* h2 = (const ulonglong2*)h_s[t & 1];
        int hb = kh * 16;
        ull a = 0, ab = 0;
#pragma unroll
        for (int i = 0; i < 16; i++) {
            ulonglong2 hv = h2[hb + i];
            a  = ffma2(w[2 * i],     hv.x, a);
            ab = ffma2(w[2 * i + 1], hv.y, ab);
        }
        float p = hadd(a) + hadd(ab);
        p += __shfl_xor_sync(0xffffffffu, p, 1);

        nh = tanhf(p + p_cur);
        if (kh == 0) h_s[(t + 1) & 1][j] = nh;                      // next-step h
        else         g_y0[((size_t)b * T_ + t) * H_ + j] = nh;      // stream out

        p_cur = p_nxt;
        int tn = (t + 2 < T_) ? (t + 2) : (T_ - 1);
        p_nxt = g_proj[x_s[tn] * H_ + j];
        __syncthreads();
    }
    if (kh == 0) hid0[b * H_ + j] = nh;
}

// ---------------------------------------------------------------------------
// Layer-1 recurrence (input projection hoisted into g_xp1). Same shape as l0.
// ---------------------------------------------------------------------------
__global__ void __launch_bounds__(256, 2)
k_l1(float* __restrict__ hid1) {
    __shared__ __align__(16) float h_s[2][128];

    int tid = threadIdx.x;
    int j = tid >> 1, kh = tid & 1;
    int b = blockIdx.x;

    extern __device__ float g_Whh1_copy[];  // fwd decl trick not needed; weights passed below
    (void)hid1;
}

// real k_l1 (with weight pointer)
__global__ void __launch_bounds__(256, 2)
k_l1w(const float* __restrict__ Whh1, float* __restrict__ hid1) {
    __shared__ __align__(16) float h_s[2][128];

    int tid = threadIdx.x;
    int j = tid >> 1, kh = tid & 1;
    int b = blockIdx.x;

    ull w[32];
    const ull* Wp = (const ull*)Whh1;
    int wbase = j * 64 + kh * 32;
#pragma unroll
    for (int i = 0; i < 32; i++) w[i] = Wp[wbase + i];

    if (tid < 128) h_s[0][tid] = 0.0f;
    __syncthreads();

    const float* xp = g_xp1 + (size_t)b * T_ * H_ + j;
    float p_cur = xp[0];
    float p_nxt = xp[H_];

    float nh = 0.0f;
    for (int t = 0; t < T_; t++) {
        const ulonglong2* h2 = (const ulonglong2*)h_s[t & 1];
        int hb = kh * 16;
        ull a = 0, ab = 0;
#pragma unroll
        for (int i = 0; i < 16; i++) {
            ulonglong2 hv = h2[hb + i];
            a  = ffma2(w[2 * i],     hv.x, a);
            ab = ffma2(w[2 * i + 1], hv.y, ab);
        }
        float p = hadd(a) + hadd(ab);
        p += __shfl_xor_sync(0xffffffffu, p, 1);

        nh = tanhf(p + p_cur);
        if (kh == 0) h_s[(t + 1) & 1][j] = nh;
        else         g_y1[((size_t)b * T_ + t) * H_ + j] = nh;

        p_cur = p_nxt;
        int tn = (t + 2 < T_) ? (t + 2) : (T_ - 1);
        p_nxt = xp[(size_t)tn * H_];
        __syncthreads();
    }
    if (kh == 0) hid1[b * H_ + j] = nh;
}

// ---------------------------------------------------------------------------
// Generic FFMA2 GEMM: out[r][v] = sum_h in[r][h]*W[v][h] + b1[v] (+ b2[v])
// 64 rows x N cols per CTA. W staged in smem with pad-65 rows (bank-safe),
// input rows staged in smem (broadcast reads). 2 CTAs/SM.
// ---------------------------------------------------------------------------
template <int N>
__global__ void __launch_bounds__(256, 2)
k_gemm(const float* __restrict__ in, const float* __restrict__ W,
       const float* __restrict__ b1, const float* __restrict__ b2,
       float* __restrict__ out) {
    extern __shared__ ull sm[];
    ull* Ws = sm;                 // [N][65]
    ull* ys = sm + N * 65;        // [64][64]
    int tid = threadIdx.x;

    const ull* Wg = (const ull*)W;
    for (int i = tid; i < N * 64; i += 256) {
        int v = i >> 6, k = i & 63;
        Ws[v * 65 + k] = Wg[i];
    }
    const ull* yg = (const ull*)in + (size_t)blockIdx.x * 64 * 64;
    for (int i = tid; i < 64 * 64; i += 256) ys[i] = yg[i];
    __syncthreads();

    constexpr int CJ = N / 16;                 // cols per thread (6 or 8)
    int tx = tid & 15, ty = tid >> 4;
    int v0 = tx * CJ, r0 = ty * 4;

    ull acc0[4][CJ], acc1[4][CJ];
#pragma unroll
    for (int ii = 0; ii < 4; ii++)
#pragma unroll
        for (int jj = 0; jj < CJ; jj++) { acc0[ii][jj] = 0; acc1[ii][jj] = 0; }

#pragma unroll 4
    for (int kp2 = 0; kp2 < 32; kp2++) {
        ulonglong2 yv[4];
#pragma unroll
        for (int ii = 0; ii < 4; ii++)
            yv[ii] = ((const ulonglong2*)(ys + (r0 + ii) * 64))[kp2];
        ull wv0[CJ], wv1[CJ];
#pragma unroll
        for (int jj = 0; jj < CJ; jj++) {
            wv0[jj] = Ws[(v0 + jj) * 65 + 2 * kp2];
            wv1[jj] = Ws[(v0 + jj) * 65 + 2 * kp2 + 1];
        }
#pragma unroll
        for (int ii = 0; ii < 4; ii++)
#pragma unroll
            for (int jj = 0; jj < CJ; jj++) {
                acc0[ii][jj] = ffma2(yv[ii].x, wv0[jj], acc0[ii][jj]);
                acc1[ii][jj] = ffma2(yv[ii].y, wv1[jj], acc1[ii][jj]);
            }
    }

    float bias[CJ];
#pragma unroll
    for (int jj = 0; jj < CJ; jj++) {
        bias[jj] = b1[v0 + jj];
        if (b2) bias[jj] += b2[v0 + jj];
    }

    size_t row0 = (size_t)blockIdx.x * 64 + r0;
#pragma unroll
    for (int ii = 0; ii < 4; ii++) {
        float r[CJ];
#pragma unroll
        for (int jj = 0; jj < CJ; jj++)
            r[jj] = hadd(acc0[ii][jj]) + hadd(acc1[ii][jj]) + bias[jj];
        float* op = out + (row0 + ii) * N + v0;
#pragma unroll
        for (int jj = 0; jj < CJ; jj += 2)
            ((float2*)op)[jj >> 1] = make_float2(r[jj], r[jj + 1]);
    }
}

// ---------------------------------------------------------------------------
extern "C" void kernel_launch(void* const* d_in, const int* in_sizes, int n_in,
                              void* d_out, int out_size) {
    const int*   x    = (const int*)d_in[0];
    const float* emb  = (const float*)d_in[1];
    const float* Wih0 = (const float*)d_in[2];
    const float* Whh0 = (const float*)d_in[3];
    const float* bih0 = (const float*)d_in[4];
    const float* bhh0 = (const float*)d_in[5];
    const float* Wih1 = (const float*)d_in[6];
    const float* Whh1 = (const float*)d_in[7];
    const float* bih1 = (const float*)d_in[8];
    const float* bhh1 = (const float*)d_in[9];
    const float* fcW  = (const float*)d_in[10];
    const float* fcb  = (const float*)d_in[11];

    float* out = (float*)d_out;
    float* hid = out + (size_t)B_ * T_ * V_;   // hidden [2,B,H] after logits

    float* y0p;  cudaGetSymbolAddress((void**)&y0p,  g_y0);
    float* xp1p; cudaGetSymbolAddress((void**)&xp1p, g_xp1);
    float* y1p;  cudaGetSymbolAddress((void**)&y1p,  g_y1);

    const int smem_xp = (128 * 65 + 64 * 64) * 8;   // 99,328 B
    const int smem_fc = (96 * 65 + 64 * 64) * 8;    // 82,688 B
    cudaFuncSetAttribute(k_gemm<128>, cudaFuncAttributeMaxDynamicSharedMemorySize, smem_xp);
    cudaFuncSetAttribute(k_gemm<96>,  cudaFuncAttributeMaxDynamicSharedMemorySize, smem_fc);

    k_proj<<<V_, H_>>>(emb, Wih0, bih0, bhh0);
    k_l0<<<B_, 256>>>(x, Whh0, hid);
    k_gemm<128><<<(B_ * T_) / 64, 256, smem_xp>>>(y0p, Wih1, bih1, bhh1, xp1p);
    k_l1w<<<B_, 256>>>(Whh1, hid + B_ * H_);
    k_gemm<96><<<(B_ * T_) / 64, 256, smem_fc>>>(y1p, fcW, fcb, nullptr, out);
}

// round 4
// speedup vs baseline: 3.0825x; 3.0825x over previous
#include <cuda_runtime.h>
#include <math.h>

#define B_ 256
#define T_ 1024
#define V_ 96
#define H_ 128

typedef unsigned long long ull;

// Device-global scratch (allocation-free per harness rules)
__device__ __align__(16) float g_proj[V_ * H_];       // emb @ W_ih0^T + b_ih0 + b_hh0
__device__ __align__(16) float g_y0[B_ * T_ * H_];    // layer-0 outputs
__device__ __align__(16) float g_xp1[B_ * T_ * H_];   // y0 @ W_ih1^T + b_ih1 + b_hh1
__device__ __align__(16) float g_y1[B_ * T_ * H_];    // layer-1 outputs

// packed fp32x2 ops (Blackwell FFMA2 / FADD2)
__device__ __forceinline__ ull ffma2(ull a, ull b, ull c) {
    ull d;
    asm("fma.rn.f32x2 %0, %1, %2, %3;" : "=l"(d) : "l"(a), "l"(b), "l"(c));
    return d;
}
__device__ __forceinline__ ull fadd2(ull a, ull b) {
    ull d;
    asm("add.rn.f32x2 %0, %1, %2;" : "=l"(d) : "l"(a), "l"(b));
    return d;
}
__device__ __forceinline__ float hadd(ull a) {
    float x, y;
    asm("mov.b64 {%0, %1}, %2;" : "=f"(x), "=f"(y) : "l"(a));
    return x + y;
}
__device__ __forceinline__ float tanh_fast(float x) {
    float y;
    asm("tanh.approx.f32 %0, %1;" : "=f"(y) : "f"(x));
    return y;
}

// ---------------------------------------------------------------------------
// Projected embedding table: g_proj[v][j] = sum_h emb[v][h]*W_ih0[j][h] + b
// ---------------------------------------------------------------------------
__global__ void k_proj(const float* __restrict__ emb, const float* __restrict__ Wih0,
                       const float* __restrict__ bih0, const float* __restrict__ bhh0) {
    __shared__ float er[H_];
    int v = blockIdx.x, j = threadIdx.x;
    er[j] = emb[v * H_ + j];
    __syncthreads();
    float s = bih0[j] + bhh0[j];
    const float* wr = Wih0 + j * H_;
#pragma unroll 8
    for (int h = 0; h < H_; h++) s += er[h] * wr[h];
    g_proj[v * H_ + j] = s;
}

// ---------------------------------------------------------------------------
// Recurrence core: thread j owns full row j of W_hh (64 ull regs), computes
// the complete dot product alone (no shfl, no cross-lane reduce).
// One barrier per step; y store issued AFTER the barrier.
// addend (proj[x_t] or xp1[t]) streamed via 2-deep register prefetch.
// ---------------------------------------------------------------------------
__global__ void __launch_bounds__(128, 3)
k_l0(const int* __restrict__ x, const float* __restrict__ Whh0, float* __restrict__ hid0) {
    __shared__ __align__(16) float h_s[2][128];
    __shared__ int x_s[T_];

    int j = threadIdx.x;
    int b = blockIdx.x;

    ull w[64];
    const ull* Wp = (const ull*)Whh0 + j * 64;
#pragma unroll
    for (int i = 0; i < 64; i++) w[i] = Wp[i];

    for (int i = j; i < T_; i += 128) x_s[i] = x[b * T_ + i];
    h_s[0][j] = 0.0f;
    __syncthreads();

    float p_cur = g_proj[x_s[0] * H_ + j];
    float p_nxt = g_proj[x_s[1] * H_ + j];

    float nh = 0.0f;
    for (int t = 0; t < T_; t++) {
        const ulonglong2* h2 = (const ulonglong2*)h_s[t & 1];
        ull a0 = 0, a1 = 0, a2 = 0, a3 = 0;
#pragma unroll
        for (int i = 0; i < 32; i += 2) {
            ulonglong2 hv = h2[i];
            a0 = ffma2(w[2 * i],     hv.x, a0);
            a1 = ffma2(w[2 * i + 1], hv.y, a1);
            ulonglong2 hw = h2[i + 1];
            a2 = ffma2(w[2 * i + 2], hw.x, a2);
            a3 = ffma2(w[2 * i + 3], hw.y, a3);
        }
        float p = hadd(fadd2(fadd2(a0, a1), fadd2(a2, a3)));

        nh = tanh_fast(p + p_cur);
        h_s[(t + 1) & 1][j] = nh;

        p_cur = p_nxt;
        int tn = (t + 2 < T_) ? (t + 2) : (T_ - 1);
        p_nxt = g_proj[x_s[tn] * H_ + j];
        __syncthreads();
        g_y0[((size_t)b * T_ + t) * H_ + j] = nh;   // post-barrier store
    }
    hid0[b * H_ + j] = nh;
}

__global__ void __launch_bounds__(128, 3)
k_l1(const float* __restrict__ Whh1, float* __restrict__ hid1) {
    __shared__ __align__(16) float h_s[2][128];

    int j = threadIdx.x;
    int b = blockIdx.x;

    ull w[64];
    const ull* Wp = (const ull*)Whh1 + j * 64;
#pragma unroll
    for (int i = 0; i < 64; i++) w[i] = Wp[i];

    h_s[0][j] = 0.0f;
    __syncthreads();

    const float* xp = g_xp1 + (size_t)b * T_ * H_ + j;
    float p_cur = xp[0];
    float p_nxt = xp[H_];

    float nh = 0.0f;
    for (int t = 0; t < T_; t++) {
        const ulonglong2* h2 = (const ulonglong2*)h_s[t & 1];
        ull a0 = 0, a1 = 0, a2 = 0, a3 = 0;
#pragma unroll
        for (int i = 0; i < 32; i += 2) {
            ulonglong2 hv = h2[i];
            a0 = ffma2(w[2 * i],     hv.x, a0);
            a1 = ffma2(w[2 * i + 1], hv.y, a1);
            ulonglong2 hw = h2[i + 1];
            a2 = ffma2(w[2 * i + 2], hw.x, a2);
            a3 = ffma2(w[2 * i + 3], hw.y, a3);
        }
        float p = hadd(fadd2(fadd2(a0, a1), fadd2(a2, a3)));

        nh = tanh_fast(p + p_cur);
        h_s[(t + 1) & 1][j] = nh;

        p_cur = p_nxt;
        int tn = (t + 2 < T_) ? (t + 2) : (T_ - 1);
        p_nxt = xp[(size_t)tn * H_];
        __syncthreads();
        g_y1[((size_t)b * T_ + t) * H_ + j] = nh;   // post-barrier store
    }
    hid1[b * H_ + j] = nh;
}

// ---------------------------------------------------------------------------
// FFMA2 GEMM: out[r][v] = sum_h in[r][h]*W[v][h] + b1[v] (+ b2[v])
// 64 rows x N cols per CTA, 256 threads, 2 CTAs/SM.
// W^T staged in smem [kp][N+1] (pad -> conflict-free compute loads:
// lane tx reads col tx+16*jj -> consecutive banks). y rows broadcast.
// ---------------------------------------------------------------------------
template <int N>
__global__ void __launch_bounds__(256, 2)
k_gemm(const float* __restrict__ in, const float* __restrict__ W,
       const float* __restrict__ b1, const float* __restrict__ b2,
       float* __restrict__ out) {
    constexpr int NP = N + 1;
    extern __shared__ ull sm[];
    ull* Ws = sm;                 // [64 kp][NP]
    ull* ys = sm + 64 * NP;       // [64 rows][64 kp]
    int tid = threadIdx.x;

    // W stage: global read coalesced (v-major), smem store 2-way conflict (pad)
    const ull* Wg = (const ull*)W;
    for (int i = tid; i < N * 64; i += 256) {
        int v = i >> 6, kp = i & 63;
        Ws[kp * NP + v] = Wg[i];
    }
    const ull* yg = (const ull*)in + (size_t)blockIdx.x * 64 * 64;
    for (int i = tid; i < 64 * 64; i += 256) ys[i] = yg[i];
    __syncthreads();

    constexpr int CJ = N / 16;    // cols per thread: 6 (N=96) or 8 (N=128)
    int tx = tid & 15, ty = tid >> 4;
    int r0 = ty * 4;

    ull acc[4][CJ];
#pragma unroll
    for (int ii = 0; ii < 4; ii++)
#pragma unroll
        for (int jj = 0; jj < CJ; jj++) acc[ii][jj] = 0;

#pragma unroll 2
    for (int kp = 0; kp < 64; kp++) {
        ull yv[4], wv[CJ];
#pragma unroll
        for (int ii = 0; ii < 4; ii++) yv[ii] = ys[(r0 + ii) * 64 + kp];   // broadcast
#pragma unroll
        for (int jj = 0; jj < CJ; jj++) wv[jj] = Ws[kp * NP + tx + 16 * jj]; // conflict-free
#pragma unroll
        for (int ii = 0; ii < 4; ii++)
#pragma unroll
            for (int jj = 0; jj < CJ; jj++)
                acc[ii][jj] = ffma2(yv[ii], wv[jj], acc[ii][jj]);
    }

    float bias[CJ];
#pragma unroll
    for (int jj = 0; jj < CJ; jj++) {
        bias[jj] = b1[tx + 16 * jj];
        if (b2) bias[jj] += b2[tx + 16 * jj];
    }

    size_t row0 = (size_t)blockIdx.x * 64 + r0;
#pragma unroll
    for (int ii = 0; ii < 4; ii++)
#pragma unroll
        for (int jj = 0; jj < CJ; jj++)
            out[(row0 + ii) * N + tx + 16 * jj] = hadd(acc[ii][jj]) + bias[jj];
}

// ---------------------------------------------------------------------------
extern "C" void kernel_launch(void* const* d_in, const int* in_sizes, int n_in,
                              void* d_out, int out_size) {
    const int*   x    = (const int*)d_in[0];
    const float* emb  = (const float*)d_in[1];
    const float* Wih0 = (const float*)d_in[2];
    const float* Whh0 = (const float*)d_in[3];
    const float* bih0 = (const float*)d_in[4];
    const float* bhh0 = (const float*)d_in[5];
    const float* Wih1 = (const float*)d_in[6];
    const float* Whh1 = (const float*)d_in[7];
    const float* bih1 = (const float*)d_in[8];
    const float* bhh1 = (const float*)d_in[9];
    const float* fcW  = (const float*)d_in[10];
    const float* fcb  = (const float*)d_in[11];

    float* out = (float*)d_out;
    float* hid = out + (size_t)B_ * T_ * V_;   // hidden [2,B,H] after logits

    float* y0p;  cudaGetSymbolAddress((void**)&y0p,  g_y0);
    float* xp1p; cudaGetSymbolAddress((void**)&xp1p, g_xp1);
    float* y1p;  cudaGetSymbolAddress((void**)&y1p,  g_y1);

    const int smem_xp = (64 * 129 + 64 * 64) * 8;   // 98,816 B
    const int smem_fc = (64 * 97  + 64 * 64) * 8;   // 82,432 B
    cudaFuncSetAttribute(k_gemm<128>, cudaFuncAttributeMaxDynamicSharedMemorySize, smem_xp);
    cudaFuncSetAttribute(k_gemm<96>,  cudaFuncAttributeMaxDynamicSharedMemorySize, smem_fc);

    k_proj<<<V_, H_>>>(emb, Wih0, bih0, bhh0);
    k_l0<<<B_, 128>>>(x, Whh0, hid);
    k_gemm<128><<<(B_ * T_) / 64, 256, smem_xp>>>(y0p, Wih1, bih1, bhh1, xp1p);
    k_l1<<<B_, 128>>>(Whh1, hid + B_ * H_);
    k_gemm<96><<<(B_ * T_) / 64, 256, smem_fc>>>(y1p, fcW, fcb, nullptr, out);
}